// round 3
// baseline (speedup 1.0000x reference)
#include <cuda_runtime.h>
#include <cstdint>

#define B_    4096
#define H_    512
#define TOBS  30
#define TPRED 60

// ------------------ device scratch (static, no runtime alloc) ------------------
__device__ float g_h0[2][B_ * H_];
__device__ float g_h1[2][B_ * H_];
__device__ float g_hd[2][B_ * H_];
__device__ float g_decin[2][B_ * 2];
// packed fragment-interleaved weights: [kb<64][g<3][jb<64][lane<32][v<2]
// value = tf32(W[g*512 + jb*8 + lane/4][kb*8 + lane%4 + 4*v])
__device__ float g_Wp[4][786432];   // {W_hh0, W_ih1, W_hh1, W_hhd}
// combined bias table per layer: [j][4] = {bih_r+bhh_r, bih_z+bhh_z, bih_n, bhh_n}
__device__ float g_b4[3][H_ * 4];

// ------------------ helpers ------------------
__device__ __forceinline__ float tf32r(float x) {
    uint32_t u;
    asm("cvt.rna.tf32.f32 %0, %1;" : "=r"(u) : "f"(x));
    return __uint_as_float(u);
}

__device__ __forceinline__ void mma8(float c[4], uint32_t a0, uint32_t a1, uint32_t a2, uint32_t a3,
                                     uint32_t b0, uint32_t b1) {
    asm volatile(
        "mma.sync.aligned.m16n8k8.row.col.f32.tf32.tf32.f32 "
        "{%0,%1,%2,%3},{%4,%5,%6,%7},{%8,%9},{%0,%1,%2,%3};"
        : "+f"(c[0]), "+f"(c[1]), "+f"(c[2]), "+f"(c[3])
        : "r"(a0), "r"(a1), "r"(a2), "r"(a3), "r"(b0), "r"(b1));
}

__device__ __forceinline__ float sigf(float v) { return 1.0f / (1.0f + __expf(-v)); }

// ------------------ prep: pack weights (tf32-rounded) + combined biases ------------------
__global__ void prep_kernel(const float* __restrict__ Whh0, const float* __restrict__ Wih1,
                            const float* __restrict__ Whh1, const float* __restrict__ Whhd,
                            const float* __restrict__ bih0, const float* __restrict__ bhh0,
                            const float* __restrict__ bih1, const float* __restrict__ bhh1,
                            const float* __restrict__ bihd, const float* __restrict__ bhhd) {
    const int NW = 4 * 786432;
    const int total = NW + 3 * 2048;
    for (int idx = blockIdx.x * blockDim.x + threadIdx.x; idx < total;
         idx += gridDim.x * blockDim.x) {
        if (idx < NW) {
            int mat = idx / 786432, o = idx % 786432;
            int kb = o / 12288, rem = o % 12288;
            int g = rem / 4096, rem2 = rem % 4096;
            int jb = rem2 / 64, l2 = rem2 % 64;
            int lane = l2 >> 1, v = l2 & 1;
            int row = g * 512 + jb * 8 + (lane >> 2);
            int k = kb * 8 + (lane & 3) + 4 * v;
            const float* Wsrc = (mat == 0) ? Whh0 : (mat == 1) ? Wih1 : (mat == 2) ? Whh1 : Whhd;
            g_Wp[mat][o] = tf32r(Wsrc[row * 512 + k]);
        } else {
            int r = idx - NW;
            int l = r / 2048, rem = r % 2048;
            int j = rem >> 2, s = rem & 3;
            const float* bi = (l == 0) ? bih0 : (l == 1) ? bih1 : bihd;
            const float* bh = (l == 0) ? bhh0 : (l == 1) ? bhh1 : bhhd;
            float v;
            if (s == 0)      v = bi[j] + bh[j];
            else if (s == 1) v = bi[512 + j] + bh[512 + j];
            else if (s == 2) v = bi[1024 + j];
            else             v = bh[1024 + j];
            g_b4[l][j * 4 + s] = v;
        }
    }
}

// zero initial hiddens + seed decoder input with x[:, 29, :2]
__global__ void init_kernel(const float* __restrict__ x) {
    int idx0 = blockIdx.x * blockDim.x + threadIdx.x;
    for (int i = idx0; i < B_ * H_; i += gridDim.x * blockDim.x) {
        g_h0[0][i] = 0.0f;
        g_h1[0][i] = 0.0f;
    }
    if (idx0 < B_ * 2) {
        int m = idx0 >> 1, o = idx0 & 1;
        g_decin[0][idx0] = x[m * 120 + 116 + o];  // x[m][29][o]
    }
}

// ------------------ pipelined tensor-core GEMM accumulation ------------------
// A chunks (128 rows x 32 cols) double-buffered in smem via cp.async;
// B fragments prefetched one k-step ahead in registers from L2.
template <int SETS, int S2>
__device__ __forceinline__ void gemm_accum(float (&acc)[SETS][2][4][4],
                                           const float* __restrict__ A,
                                           const float* __restrict__ Wp,
                                           int m0, int jb0, int wm,
                                           int lane, int tid, float (*sA)[36]) {
    uint32_t sbase = (uint32_t)__cvta_generic_to_shared(&sA[0][0]);
    // prologue: issue chunk 0 into buffer 0
    {
#pragma unroll
        for (int i = 0; i < 4; ++i) {
            int ff = tid + i * 256;
            int row = ff >> 3, c4 = (ff & 7) << 2;
            uint32_t sa = sbase + (uint32_t)((row * 36 + c4) * 4);
            const float* g = A + (m0 + row) * 512 + c4;
            asm volatile("cp.async.cg.shared.global [%0], [%1], 16;" :: "r"(sa), "l"(g));
        }
        asm volatile("cp.async.commit_group;" ::: "memory");
    }
    const float* Wb = Wp + lane * 2 + jb0 * 64;
    float2 bc[3][4], bn[3][4];
#pragma unroll
    for (int g = 0; g < 3; ++g)
#pragma unroll
        for (int nf = 0; nf < 4; ++nf)
            bc[g][nf] = *reinterpret_cast<const float2*>(Wb + g * 4096 + nf * 64);

    for (int c = 0; c < 16; ++c) {
        asm volatile("cp.async.wait_group 0;" ::: "memory");
        __syncthreads();
        if (c + 1 < 16) {
            int b = (c + 1) & 1;
#pragma unroll
            for (int i = 0; i < 4; ++i) {
                int ff = tid + i * 256;
                int row = ff >> 3, c4 = (ff & 7) << 2;
                uint32_t sa = sbase + (uint32_t)(((b * 128 + row) * 36 + c4) * 4);
                const float* g = A + (m0 + row) * 512 + (c + 1) * 32 + c4;
                asm volatile("cp.async.cg.shared.global [%0], [%1], 16;" :: "r"(sa), "l"(g));
            }
            asm volatile("cp.async.commit_group;" ::: "memory");
        }
        const float (*sC)[36] = sA + (c & 1) * 128;
#pragma unroll
        for (int ks = 0; ks < 4; ++ks) {
            int kb = c * 4 + ks;
            if (kb < 63) {  // prefetch next k-step's B fragments
                const float* p = Wb + (kb + 1) * 12288;
#pragma unroll
                for (int g = 0; g < 3; ++g)
#pragma unroll
                    for (int nf = 0; nf < 4; ++nf)
                        bn[g][nf] = *reinterpret_cast<const float2*>(p + g * 4096 + nf * 64);
            }
            int kk = ks * 8 + (lane & 3);
            uint32_t a[2][4];
#pragma unroll
            for (int mf = 0; mf < 2; ++mf) {
                int rb = wm * 32 + mf * 16 + (lane >> 2);
                a[mf][0] = __float_as_uint(tf32r(sC[rb][kk]));
                a[mf][1] = __float_as_uint(tf32r(sC[rb + 8][kk]));
                a[mf][2] = __float_as_uint(tf32r(sC[rb][kk + 4]));
                a[mf][3] = __float_as_uint(tf32r(sC[rb + 8][kk + 4]));
            }
#pragma unroll
            for (int g = 0; g < 3; ++g) {
                const int s = (g == 2) ? S2 : g;
#pragma unroll
                for (int nf = 0; nf < 4; ++nf) {
                    uint32_t b0 = __float_as_uint(bc[g][nf].x);
                    uint32_t b1 = __float_as_uint(bc[g][nf].y);
                    mma8(acc[s][0][nf], a[0][0], a[0][1], a[0][2], a[0][3], b0, b1);
                    mma8(acc[s][1][nf], a[1][0], a[1][1], a[1][2], a[1][3], b0, b1);
                }
            }
#pragma unroll
            for (int g = 0; g < 3; ++g)
#pragma unroll
                for (int nf = 0; nf < 4; ++nf)
                    bc[g][nf] = bn[g][nf];
        }
    }
}

// ------------------ fused GRU step body ------------------
// MODE 0: layer0 (x K=4 scalar ih, tensor hh). MODE 1: layer1 (tensor ih + tensor hh).
// MODE 2: decoder (decin K=2 scalar ih, tensor hh).
template <int MODE>
__device__ __forceinline__ void gru_body(int t, const float* __restrict__ x,
                                         const float* __restrict__ Wraw,
                                         float (*sA)[36]) {
    int tid = threadIdx.x, lane = tid & 31, w = tid >> 5;
    int wm = w & 3, wn = w >> 2;                // 4 M-warps x 2 N-warps
    int m0 = blockIdx.x * 128, n0 = blockIdx.y * 64;
    int jb0 = (n0 >> 3) + wn * 4;

    const float* hin;
    const float* xin = nullptr;
    float* hout;
    const float* Wp_hh;
    const float* Wp_ih = nullptr;
    const float* b4;
    if constexpr (MODE == 0) {
        hin = g_h0[t & 1]; hout = g_h0[(t + 1) & 1];
        Wp_hh = g_Wp[0]; b4 = g_b4[0];
    } else if constexpr (MODE == 1) {
        hin = g_h1[t & 1]; hout = g_h1[(t + 1) & 1];
        xin = g_h0[(t + 1) & 1];
        Wp_ih = g_Wp[1]; Wp_hh = g_Wp[2]; b4 = g_b4[1];
    } else {
        hin = (t == 0) ? g_h1[0] : g_hd[t & 1];
        hout = g_hd[(t + 1) & 1];
        xin = g_decin[t & 1];
        Wp_hh = g_Wp[3]; b4 = g_b4[2];
    }

    constexpr int SETS = (MODE == 1) ? 4 : 3;
    float acc[SETS][2][4][4];
#pragma unroll
    for (int s = 0; s < SETS; ++s)
#pragma unroll
        for (int mf = 0; mf < 2; ++mf)
#pragma unroll
            for (int nf = 0; nf < 4; ++nf)
#pragma unroll
                for (int q = 0; q < 4; ++q) acc[s][mf][nf][q] = 0.0f;

    if constexpr (MODE == 1) {
        gemm_accum<SETS, 2>(acc, xin, Wp_ih, m0, jb0, wm, lane, tid, sA);  // i_n -> set 2
        gemm_accum<SETS, 3>(acc, hin, Wp_hh, m0, jb0, wm, lane, tid, sA);  // h_n -> set 3
    } else {
        gemm_accum<SETS, 2>(acc, hin, Wp_hh, m0, jb0, wm, lane, tid, sA);  // h_n -> set 2
    }

    // ------------- epilogue: gates + h update -------------
#pragma unroll
    for (int mf = 0; mf < 2; ++mf) {
#pragma unroll
        for (int rr = 0; rr < 2; ++rr) {
            int m = m0 + wm * 32 + mf * 16 + rr * 8 + (lane >> 2);
            float4 xr = make_float4(0.f, 0.f, 0.f, 0.f);
            float2 x2 = make_float2(0.f, 0.f);
            if constexpr (MODE == 0) xr = *reinterpret_cast<const float4*>(&x[m * 120 + t * 4]);
            if constexpr (MODE == 2) x2 = *reinterpret_cast<const float2*>(&xin[m * 2]);
#pragma unroll
            for (int nf = 0; nf < 4; ++nf) {
                int j = n0 + wn * 32 + nf * 8 + (lane & 3) * 2;
                float2 ho = *reinterpret_cast<const float2*>(&hin[m * 512 + j]);
                float hnew[2];
#pragma unroll
                for (int cc = 0; cc < 2; ++cc) {
                    int jj = j + cc;
                    float4 bb = *reinterpret_cast<const float4*>(&b4[jj * 4]);
                    int q = rr * 2 + cc;
                    float vr = acc[0][mf][nf][q];
                    float vz = acc[1][mf][nf][q];
                    float gir = 0.f, giz = 0.f, gin = 0.f;
                    if constexpr (MODE == 0) {
                        float4 wr = *reinterpret_cast<const float4*>(&Wraw[jj * 4]);
                        float4 wz = *reinterpret_cast<const float4*>(&Wraw[(jj + 512) * 4]);
                        float4 wn4 = *reinterpret_cast<const float4*>(&Wraw[(jj + 1024) * 4]);
                        gir = xr.x * wr.x + xr.y * wr.y + xr.z * wr.z + xr.w * wr.w;
                        giz = xr.x * wz.x + xr.y * wz.y + xr.z * wz.z + xr.w * wz.w;
                        gin = xr.x * wn4.x + xr.y * wn4.y + xr.z * wn4.z + xr.w * wn4.w;
                    } else if constexpr (MODE == 2) {
                        float2 wr = *reinterpret_cast<const float2*>(&Wraw[jj * 2]);
                        float2 wz = *reinterpret_cast<const float2*>(&Wraw[(jj + 512) * 2]);
                        float2 wn2 = *reinterpret_cast<const float2*>(&Wraw[(jj + 1024) * 2]);
                        gir = x2.x * wr.x + x2.y * wr.y;
                        giz = x2.x * wz.x + x2.y * wz.y;
                        gin = x2.x * wn2.x + x2.y * wn2.y;
                    }
                    float rg = sigf(vr + gir + bb.x);
                    float zg = sigf(vz + giz + bb.y);
                    float in_term, hn_term;
                    if constexpr (MODE == 1) {
                        in_term = acc[2][mf][nf][q] + bb.z;
                        hn_term = acc[3][mf][nf][q] + bb.w;
                    } else {
                        in_term = gin + bb.z;
                        hn_term = acc[2][mf][nf][q] + bb.w;
                    }
                    float ng = tanhf(in_term + rg * hn_term);
                    float hprev = cc ? ho.y : ho.x;
                    hnew[cc] = (1.0f - zg) * ng + zg * hprev;
                }
                *reinterpret_cast<float2*>(&hout[m * 512 + j]) = make_float2(hnew[0], hnew[1]);
            }
        }
    }
}

// encoder fused step: z==0 -> layer0 at time t; z==1 -> layer1 at time t-1 (independent)
__global__ void __launch_bounds__(256, 1)
enc_step(int t, const float* __restrict__ x, const float* __restrict__ Wih0) {
    __shared__ float sA[256][36];
    if (blockIdx.z == 0) {
        if (t >= TOBS) return;
        gru_body<0>(t, x, Wih0, sA);
    } else {
        if (t == 0) return;
        gru_body<1>(t - 1, x, nullptr, sA);
    }
}

__global__ void __launch_bounds__(256, 1)
dec_step(int t, const float* __restrict__ Wihd) {
    __shared__ float sA[256][36];
    gru_body<2>(t, nullptr, Wihd, sA);
}

// ------------------ decoder FC: pred = h @ W_fc.T + b_fc; feed back ------------------
__global__ void fc_kernel(int td, const float* __restrict__ Wfc, const float* __restrict__ bfc,
                          float* __restrict__ out) {
    int gw = (blockIdx.x * blockDim.x + threadIdx.x) >> 5;  // one warp per batch row
    int lane = threadIdx.x & 31;
    if (gw >= B_) return;
    const float* h = g_hd[(td + 1) & 1] + gw * 512;
    float s0 = 0.f, s1 = 0.f;
#pragma unroll
    for (int i = 0; i < 16; ++i) {
        float hv = h[lane + 32 * i];
        s0 += hv * Wfc[lane + 32 * i];
        s1 += hv * Wfc[512 + lane + 32 * i];
    }
#pragma unroll
    for (int o = 16; o; o >>= 1) {
        s0 += __shfl_xor_sync(0xffffffffu, s0, o);
        s1 += __shfl_xor_sync(0xffffffffu, s1, o);
    }
    if (lane == 0) {
        s0 += bfc[0]; s1 += bfc[1];
        out[gw * 120 + td * 2] = s0;
        out[gw * 120 + td * 2 + 1] = s1;
        float* dn = g_decin[(td + 1) & 1];
        dn[gw * 2] = s0;
        dn[gw * 2 + 1] = s1;
    }
}

// ------------------ launch ------------------
extern "C" void kernel_launch(void* const* d_in, const int* in_sizes, int n_in,
                              void* d_out, int out_size) {
    (void)in_sizes; (void)n_in; (void)out_size;
    const float* x    = (const float*)d_in[0];
    const float* Wih0 = (const float*)d_in[1];
    const float* Whh0 = (const float*)d_in[2];
    const float* bih0 = (const float*)d_in[3];
    const float* bhh0 = (const float*)d_in[4];
    const float* Wih1 = (const float*)d_in[5];
    const float* Whh1 = (const float*)d_in[6];
    const float* bih1 = (const float*)d_in[7];
    const float* bhh1 = (const float*)d_in[8];
    const float* Wihd = (const float*)d_in[9];
    const float* Whhd = (const float*)d_in[10];
    const float* bihd = (const float*)d_in[11];
    const float* bhhd = (const float*)d_in[12];
    const float* Wfc  = (const float*)d_in[13];
    const float* bfc  = (const float*)d_in[14];
    float* out = (float*)d_out;

    prep_kernel<<<1024, 256>>>(Whh0, Wih1, Whh1, Whhd,
                               bih0, bhh0, bih1, bhh1, bihd, bhhd);
    init_kernel<<<2048, 256>>>(x);

    dim3 egrid(32, 8, 2);  // 4096/128 x 512/64 x {layer0(t), layer1(t-1)}
    for (int t = 0; t <= TOBS; ++t) {
        enc_step<<<egrid, 256>>>(t, x, Wih0);
    }
    dim3 dgrid(32, 8);
    for (int td = 0; td < TPRED; ++td) {
        dec_step<<<dgrid, 256>>>(td, Wihd);
        fc_kernel<<<512, 256>>>(td, Wfc, bfc, out);
    }
}

// round 4
// speedup vs baseline: 1.3020x; 1.3020x over previous
#include <cuda_runtime.h>
#include <cstdint>

#define B_    4096
#define H_    512
#define TOBS  30
#define TPRED 60

// ------------------ device scratch (static, no runtime alloc) ------------------
__device__ float g_h0[2][B_ * H_];
__device__ float g_h1[2][B_ * H_];
__device__ float g_hd[2][B_ * H_];
__device__ float g_decin[2][B_ * 2];
// packed fragment-interleaved weights: [kb<64][g<3][jb<64][lane<32][v<2]
// value = tf32(W[g*512 + jb*8 + lane/4][kb*8 + lane%4 + 4*v])
__device__ float g_Wp[4][786432];   // {W_hh0, W_ih1, W_hh1, W_hhd}
// combined bias table per layer: [j][4] = {bih_r+bhh_r, bih_z+bhh_z, bih_n, bhh_n}
__device__ float g_b4[3][H_ * 4];

// ------------------ helpers ------------------
__device__ __forceinline__ float tf32r(float x) {
    uint32_t u;
    asm("cvt.rna.tf32.f32 %0, %1;" : "=r"(u) : "f"(x));
    return __uint_as_float(u);
}

__device__ __forceinline__ void mma8(float c[4], uint32_t a0, uint32_t a1, uint32_t a2, uint32_t a3,
                                     uint32_t b0, uint32_t b1) {
    asm volatile(
        "mma.sync.aligned.m16n8k8.row.col.f32.tf32.tf32.f32 "
        "{%0,%1,%2,%3},{%4,%5,%6,%7},{%8,%9},{%0,%1,%2,%3};"
        : "+f"(c[0]), "+f"(c[1]), "+f"(c[2]), "+f"(c[3])
        : "r"(a0), "r"(a1), "r"(a2), "r"(a3), "r"(b0), "r"(b1));
}

__device__ __forceinline__ float sigf(float v) { return 1.0f / (1.0f + __expf(-v)); }

// ------------------ prep: pack weights (tf32-rounded) + combined biases ------------------
__global__ void prep_kernel(const float* __restrict__ Whh0, const float* __restrict__ Wih1,
                            const float* __restrict__ Whh1, const float* __restrict__ Whhd,
                            const float* __restrict__ bih0, const float* __restrict__ bhh0,
                            const float* __restrict__ bih1, const float* __restrict__ bhh1,
                            const float* __restrict__ bihd, const float* __restrict__ bhhd) {
    const int NW = 4 * 786432;
    const int total = NW + 3 * 2048;
    for (int idx = blockIdx.x * blockDim.x + threadIdx.x; idx < total;
         idx += gridDim.x * blockDim.x) {
        if (idx < NW) {
            int mat = idx / 786432, o = idx % 786432;
            int kb = o / 12288, rem = o % 12288;
            int g = rem / 4096, rem2 = rem % 4096;
            int jb = rem2 / 64, l2 = rem2 % 64;
            int lane = l2 >> 1, v = l2 & 1;
            int row = g * 512 + jb * 8 + (lane >> 2);
            int k = kb * 8 + (lane & 3) + 4 * v;
            const float* Wsrc = (mat == 0) ? Whh0 : (mat == 1) ? Wih1 : (mat == 2) ? Whh1 : Whhd;
            g_Wp[mat][o] = tf32r(Wsrc[row * 512 + k]);
        } else {
            int r = idx - NW;
            int l = r / 2048, rem = r % 2048;
            int j = rem >> 2, s = rem & 3;
            const float* bi = (l == 0) ? bih0 : (l == 1) ? bih1 : bihd;
            const float* bh = (l == 0) ? bhh0 : (l == 1) ? bhh1 : bhhd;
            float v;
            if (s == 0)      v = bi[j] + bh[j];
            else if (s == 1) v = bi[512 + j] + bh[512 + j];
            else if (s == 2) v = bi[1024 + j];
            else             v = bh[1024 + j];
            g_b4[l][j * 4 + s] = v;
        }
    }
}

// zero initial hiddens + seed decoder input with x[:, 29, :2]
__global__ void init_kernel(const float* __restrict__ x) {
    int idx0 = blockIdx.x * blockDim.x + threadIdx.x;
    for (int i = idx0; i < B_ * H_; i += gridDim.x * blockDim.x) {
        g_h0[0][i] = 0.0f;
        g_h1[0][i] = 0.0f;
    }
    if (idx0 < B_ * 2) {
        int m = idx0 >> 1, o = idx0 & 1;
        g_decin[0][idx0] = x[m * 120 + 116 + o];  // x[m][29][o]
    }
}

// ------------------ tensor-core GEMM accumulation ------------------
// 16 warps (wm 0..3 x wn 0..3), warp tile 32m x 16n per gate.
// A chunks (128 rows x 64 cols) double-buffered in smem via cp.async.
template <int SETS, int S2>
__device__ __forceinline__ void gemm_accum(float (&acc)[SETS][2][2][4],
                                           const float* __restrict__ A,
                                           const float* __restrict__ Wp,
                                           int m0, int jb0, int wm,
                                           int lane, int tid, float (*sA)[68]) {
    uint32_t sbase = (uint32_t)__cvta_generic_to_shared(&sA[0][0]);
    // chunk loader: 128 rows x 64 cols = 2048 float4, 512 threads x 4 each
    auto load_chunk = [&](int c, int b) {
#pragma unroll
        for (int i = 0; i < 4; ++i) {
            int ff = tid + i * 512;
            int row = ff >> 4, c4 = (ff & 15) << 2;
            uint32_t sa = sbase + (uint32_t)(((b * 128 + row) * 68 + c4) * 4);
            const float* g = A + (m0 + row) * 512 + c * 64 + c4;
            asm volatile("cp.async.cg.shared.global [%0], [%1], 16;" :: "r"(sa), "l"(g));
        }
        asm volatile("cp.async.commit_group;" ::: "memory");
    };
    load_chunk(0, 0);

    for (int c = 0; c < 8; ++c) {
        asm volatile("cp.async.wait_group 0;" ::: "memory");
        __syncthreads();
        if (c < 7) load_chunk(c + 1, (c + 1) & 1);
        const float (*sC)[68] = sA + (c & 1) * 128;
#pragma unroll
        for (int ks = 0; ks < 8; ++ks) {
            int kb = c * 8 + ks;
            int kk = ks * 8 + (lane & 3);
            uint32_t a[2][4];
#pragma unroll
            for (int mf = 0; mf < 2; ++mf) {
                int rb = wm * 32 + mf * 16 + (lane >> 2);
                a[mf][0] = __float_as_uint(tf32r(sC[rb][kk]));
                a[mf][1] = __float_as_uint(tf32r(sC[rb + 8][kk]));
                a[mf][2] = __float_as_uint(tf32r(sC[rb][kk + 4]));
                a[mf][3] = __float_as_uint(tf32r(sC[rb + 8][kk + 4]));
            }
            const float* bp = Wp + kb * 12288 + lane * 2;
#pragma unroll
            for (int g = 0; g < 3; ++g) {
                const int s = (g == 2) ? S2 : g;
#pragma unroll
                for (int nf = 0; nf < 2; ++nf) {
                    float2 bv = *reinterpret_cast<const float2*>(bp + (g * 64 + jb0 + nf) * 64);
                    uint32_t b0 = __float_as_uint(bv.x), b1 = __float_as_uint(bv.y);
                    mma8(acc[s][0][nf], a[0][0], a[0][1], a[0][2], a[0][3], b0, b1);
                    mma8(acc[s][1][nf], a[1][0], a[1][1], a[1][2], a[1][3], b0, b1);
                }
            }
        }
    }
}

// ------------------ fused GRU step body ------------------
// MODE 0: layer0 (x K=4 scalar ih, tensor hh). MODE 1: layer1 (tensor ih + tensor hh).
// MODE 2: decoder (decin K=2 scalar ih, tensor hh).
template <int MODE>
__device__ __forceinline__ void gru_body(int t, const float* __restrict__ x,
                                         const float* __restrict__ Wraw,
                                         float (*sA)[68]) {
    int tid = threadIdx.x, lane = tid & 31, w = tid >> 5;
    int wm = w & 3, wn = w >> 2;                // 4 M-warps x 4 N-warps
    int m0 = blockIdx.x * 128, n0 = blockIdx.y * 64;
    int jb0 = (n0 >> 3) + wn * 2;

    const float* hin;
    const float* xin = nullptr;
    float* hout;
    const float* Wp_hh;
    const float* Wp_ih = nullptr;
    const float* b4;
    if constexpr (MODE == 0) {
        hin = g_h0[t & 1]; hout = g_h0[(t + 1) & 1];
        Wp_hh = g_Wp[0]; b4 = g_b4[0];
    } else if constexpr (MODE == 1) {
        hin = g_h1[t & 1]; hout = g_h1[(t + 1) & 1];
        xin = g_h0[(t + 1) & 1];
        Wp_ih = g_Wp[1]; Wp_hh = g_Wp[2]; b4 = g_b4[1];
    } else {
        hin = (t == 0) ? g_h1[0] : g_hd[t & 1];
        hout = g_hd[(t + 1) & 1];
        xin = g_decin[t & 1];
        Wp_hh = g_Wp[3]; b4 = g_b4[2];
    }

    constexpr int SETS = (MODE == 1) ? 4 : 3;
    float acc[SETS][2][2][4];
#pragma unroll
    for (int s = 0; s < SETS; ++s)
#pragma unroll
        for (int mf = 0; mf < 2; ++mf)
#pragma unroll
            for (int nf = 0; nf < 2; ++nf)
#pragma unroll
                for (int q = 0; q < 4; ++q) acc[s][mf][nf][q] = 0.0f;

    if constexpr (MODE == 1) {
        gemm_accum<SETS, 2>(acc, xin, Wp_ih, m0, jb0, wm, lane, tid, sA);  // i_n -> set 2
        gemm_accum<SETS, 3>(acc, hin, Wp_hh, m0, jb0, wm, lane, tid, sA);  // h_n -> set 3
    } else {
        gemm_accum<SETS, 2>(acc, hin, Wp_hh, m0, jb0, wm, lane, tid, sA);  // h_n -> set 2
    }

    // ------------- epilogue: gates + h update -------------
#pragma unroll
    for (int mf = 0; mf < 2; ++mf) {
#pragma unroll
        for (int rr = 0; rr < 2; ++rr) {
            int m = m0 + wm * 32 + mf * 16 + rr * 8 + (lane >> 2);
            float4 xr = make_float4(0.f, 0.f, 0.f, 0.f);
            float2 x2 = make_float2(0.f, 0.f);
            if constexpr (MODE == 0) xr = *reinterpret_cast<const float4*>(&x[m * 120 + t * 4]);
            if constexpr (MODE == 2) x2 = *reinterpret_cast<const float2*>(&xin[m * 2]);
#pragma unroll
            for (int nf = 0; nf < 2; ++nf) {
                int j = n0 + wn * 16 + nf * 8 + (lane & 3) * 2;
                float2 ho = *reinterpret_cast<const float2*>(&hin[m * 512 + j]);
                float hnew[2];
#pragma unroll
                for (int cc = 0; cc < 2; ++cc) {
                    int jj = j + cc;
                    float4 bb = *reinterpret_cast<const float4*>(&b4[jj * 4]);
                    int q = rr * 2 + cc;
                    float vr = acc[0][mf][nf][q];
                    float vz = acc[1][mf][nf][q];
                    float gir = 0.f, giz = 0.f, gin = 0.f;
                    if constexpr (MODE == 0) {
                        float4 wr = *reinterpret_cast<const float4*>(&Wraw[jj * 4]);
                        float4 wz = *reinterpret_cast<const float4*>(&Wraw[(jj + 512) * 4]);
                        float4 wn4 = *reinterpret_cast<const float4*>(&Wraw[(jj + 1024) * 4]);
                        gir = xr.x * wr.x + xr.y * wr.y + xr.z * wr.z + xr.w * wr.w;
                        giz = xr.x * wz.x + xr.y * wz.y + xr.z * wz.z + xr.w * wz.w;
                        gin = xr.x * wn4.x + xr.y * wn4.y + xr.z * wn4.z + xr.w * wn4.w;
                    } else if constexpr (MODE == 2) {
                        float2 wr = *reinterpret_cast<const float2*>(&Wraw[jj * 2]);
                        float2 wz = *reinterpret_cast<const float2*>(&Wraw[(jj + 512) * 2]);
                        float2 wn2 = *reinterpret_cast<const float2*>(&Wraw[(jj + 1024) * 2]);
                        gir = x2.x * wr.x + x2.y * wr.y;
                        giz = x2.x * wz.x + x2.y * wz.y;
                        gin = x2.x * wn2.x + x2.y * wn2.y;
                    }
                    float rg = sigf(vr + gir + bb.x);
                    float zg = sigf(vz + giz + bb.y);
                    float in_term, hn_term;
                    if constexpr (MODE == 1) {
                        in_term = acc[2][mf][nf][q] + bb.z;
                        hn_term = acc[3][mf][nf][q] + bb.w;
                    } else {
                        in_term = gin + bb.z;
                        hn_term = acc[2][mf][nf][q] + bb.w;
                    }
                    float ng = tanhf(in_term + rg * hn_term);
                    float hprev = cc ? ho.y : ho.x;
                    hnew[cc] = (1.0f - zg) * ng + zg * hprev;
                }
                *reinterpret_cast<float2*>(&hout[m * 512 + j]) = make_float2(hnew[0], hnew[1]);
            }
        }
    }
}

template <int MODE>
__global__ void __launch_bounds__(512, 1)
gru_step(int t, const float* __restrict__ x, const float* __restrict__ Wraw) {
    extern __shared__ float smem_dyn[];
    float (*sA)[68] = reinterpret_cast<float(*)[68]>(smem_dyn);
    gru_body<MODE>(t, x, Wraw, sA);
}

// ------------------ decoder FC: pred = h @ W_fc.T + b_fc; feed back ------------------
__global__ void fc_kernel(int td, const float* __restrict__ Wfc, const float* __restrict__ bfc,
                          float* __restrict__ out) {
    int gw = (blockIdx.x * blockDim.x + threadIdx.x) >> 5;  // one warp per batch row
    int lane = threadIdx.x & 31;
    if (gw >= B_) return;
    const float* h = g_hd[(td + 1) & 1] + gw * 512;
    float s0 = 0.f, s1 = 0.f;
#pragma unroll
    for (int i = 0; i < 16; ++i) {
        float hv = h[lane + 32 * i];
        s0 += hv * Wfc[lane + 32 * i];
        s1 += hv * Wfc[512 + lane + 32 * i];
    }
#pragma unroll
    for (int o = 16; o; o >>= 1) {
        s0 += __shfl_xor_sync(0xffffffffu, s0, o);
        s1 += __shfl_xor_sync(0xffffffffu, s1, o);
    }
    if (lane == 0) {
        s0 += bfc[0]; s1 += bfc[1];
        out[gw * 120 + td * 2] = s0;
        out[gw * 120 + td * 2 + 1] = s1;
        float* dn = g_decin[(td + 1) & 1];
        dn[gw * 2] = s0;
        dn[gw * 2 + 1] = s1;
    }
}

// ------------------ launch ------------------
extern "C" void kernel_launch(void* const* d_in, const int* in_sizes, int n_in,
                              void* d_out, int out_size) {
    (void)in_sizes; (void)n_in; (void)out_size;
    const float* x    = (const float*)d_in[0];
    const float* Wih0 = (const float*)d_in[1];
    const float* Whh0 = (const float*)d_in[2];
    const float* bih0 = (const float*)d_in[3];
    const float* bhh0 = (const float*)d_in[4];
    const float* Wih1 = (const float*)d_in[5];
    const float* Whh1 = (const float*)d_in[6];
    const float* bih1 = (const float*)d_in[7];
    const float* bhh1 = (const float*)d_in[8];
    const float* Wihd = (const float*)d_in[9];
    const float* Whhd = (const float*)d_in[10];
    const float* bihd = (const float*)d_in[11];
    const float* bhhd = (const float*)d_in[12];
    const float* Wfc  = (const float*)d_in[13];
    const float* bfc  = (const float*)d_in[14];
    float* out = (float*)d_out;

    const int SMEM = 2 * 128 * 68 * 4;  // 69632 B dynamic smem
    cudaFuncSetAttribute(gru_step<0>, cudaFuncAttributeMaxDynamicSharedMemorySize, SMEM);
    cudaFuncSetAttribute(gru_step<1>, cudaFuncAttributeMaxDynamicSharedMemorySize, SMEM);
    cudaFuncSetAttribute(gru_step<2>, cudaFuncAttributeMaxDynamicSharedMemorySize, SMEM);

    prep_kernel<<<1024, 256>>>(Whh0, Wih1, Whh1, Whhd,
                               bih0, bhh0, bih1, bhh1, bihd, bhhd);
    init_kernel<<<2048, 256>>>(x);

    dim3 grid(32, 8);  // 4096/128 x 512/64
    for (int t = 0; t < TOBS; ++t) {
        gru_step<0><<<grid, 512, SMEM>>>(t, x, Wih0);
        gru_step<1><<<grid, 512, SMEM>>>(t, x, (const float*)nullptr);
    }
    for (int td = 0; td < TPRED; ++td) {
        gru_step<2><<<grid, 512, SMEM>>>(td, nullptr, Wihd);
        fc_kernel<<<512, 256>>>(td, Wfc, bfc, out);
    }
}